// round 14
// baseline (speedup 1.0000x reference)
#include <cuda_runtime.h>
#include <math_constants.h>

#define V  50000
#define E  300
#define H  256
#define R  2048
#define L0 128
#define LR 64
#define S  2049          // 1 + R
#define G3 768           // 3*H

#define NC     8         // CTAs per cluster (one cluster per direction)
#define DPC    32        // h-dims per CTA
#define GRU_T  384       // 12 warps x 8 rows = 96 rows per CTA

// ---------------- scratch (device globals; no allocation allowed) -------------
__device__ float g_X[S * E];
__device__ float g_gi_f[S * G3];
__device__ float g_gi_b[S * G3];
__device__ float g_ys_f[S * H];
__device__ float g_ys_b[S * H];

// ---------------- small PTX helpers ------------------------------------------
__device__ __forceinline__ unsigned long long pk2(float lo, float hi) {
    unsigned long long r;
    asm("mov.b64 %0, {%1, %2};" : "=l"(r) : "f"(lo), "f"(hi));
    return r;
}
__device__ __forceinline__ float unpk_sum(unsigned long long v) {
    float a, b;
    asm("mov.b64 {%0, %1}, %2;" : "=f"(a), "=f"(b) : "l"(v));
    return a + b;
}
__device__ __forceinline__ unsigned long long ffma2(unsigned long long a,
                                                    unsigned long long b,
                                                    unsigned long long c) {
    unsigned long long d;
    asm("fma.rn.f32x2 %0, %1, %2, %3;" : "=l"(d) : "l"(a), "l"(b), "l"(c));
    return d;
}
__device__ __forceinline__ unsigned long long fadd2(unsigned long long a,
                                                    unsigned long long b) {
    unsigned long long d;
    asm("add.rn.f32x2 %0, %1, %2;" : "=l"(d) : "l"(a), "l"(b));
    return d;
}
__device__ __forceinline__ unsigned smem_u32(const void* p) {
    return (unsigned)__cvta_generic_to_shared(p);
}
__device__ __forceinline__ void mbar_init(unsigned addr, unsigned count) {
    asm volatile("mbarrier.init.shared.b64 [%0], %1;" :: "r"(addr), "r"(count) : "memory");
}
__device__ __forceinline__ void mbar_wait_cluster(unsigned addr, unsigned parity) {
    unsigned done;
    do {
        asm volatile(
            "{\n\t.reg .pred p;\n\t"
            "mbarrier.try_wait.parity.acquire.cluster.shared::cta.b64 p, [%1], %2, 0x989680;\n\t"
            "selp.b32 %0, 1, 0, p;\n\t}"
            : "=r"(done) : "r"(addr), "r"(parity) : "memory");
    } while (!done);
}
__device__ __forceinline__ unsigned cluster_rank() {
    unsigned r;
    asm("mov.u32 %0, %%cluster_ctarank;" : "=r"(r));
    return r;
}
__device__ __forceinline__ unsigned mapa_u32(unsigned addr, unsigned rank) {
    unsigned rem;
    asm("mapa.shared::cluster.u32 %0, %1, %2;" : "=r"(rem) : "r"(addr), "r"(rank));
    return rem;
}
__device__ __forceinline__ void st_cluster_f32(unsigned addr, float v) {
    asm volatile("st.shared::cluster.f32 [%0], %1;" :: "r"(addr), "f"(v) : "memory");
}
// plain (non-release) remote arrive — the R4-verified fast path
__device__ __forceinline__ void mbar_arrive_remote(unsigned addr) {
    asm volatile("mbarrier.arrive.shared::cluster.b64 _, [%0];" :: "r"(addr) : "memory");
}
__device__ __forceinline__ void cluster_sync() {
    asm volatile("barrier.cluster.arrive.aligned;" ::: "memory");
    asm volatile("barrier.cluster.wait.aligned;" ::: "memory");
}
__device__ __forceinline__ void bar_arrive_1() {
    asm volatile("bar.arrive 1, %0;" :: "r"(GRU_T) : "memory");
}
__device__ __forceinline__ void bar_sync_1() {
    asm volatile("bar.sync 1, %0;" :: "r"(GRU_T) : "memory");
}
// HW tanh (sm_75+): single special-function op, ~16 cyc
__device__ __forceinline__ float tanh_hw(float x) {
    float y;
    asm("tanh.approx.f32 %0, %1;" : "=f"(y) : "f"(x));
    return y;
}
// sigmoid via HW tanh: sigmoid(x) = 0.5*tanh(x/2) + 0.5
__device__ __forceinline__ float fsigmoid_hw(float x) {
    return fmaf(0.5f, tanh_hw(0.5f * x), 0.5f);
}

// ---------------- kernel 1: embedding sums -> X -------------------------------
__global__ void embed_kernel(const int* __restrict__ orig,
                             const int* __restrict__ reply,
                             const int* __restrict__ lens,
                             const float* __restrict__ embed) {
    int t = blockIdx.x;
    int e = threadIdx.x;
    if (e >= E) return;
    float acc = 0.f;
    if (t == 0) {
        #pragma unroll 4
        for (int l = 0; l < L0; ++l) {
            int tok = orig[l];
            acc += embed[(long long)tok * E + e];
        }
    } else {
        int r = t - 1;
        int len = lens[r];
        const int* rt = reply + r * LR;
        #pragma unroll 4
        for (int l = 0; l < len; ++l) {
            int tok = rt[l];
            acc += embed[(long long)tok * E + e];
        }
    }
    g_X[t * E + e] = acc;
}

// ---------------- kernel 2: gi GEMMs (both directions) ------------------------
#define TT 32
#define RR 64
#define KC 32
__global__ void gi_kernel(const float* __restrict__ Wf, const float* __restrict__ bf,
                          const float* __restrict__ Wb, const float* __restrict__ bb) {
    int dir = blockIdx.z;
    const float* W    = dir ? Wb : Wf;
    const float* bias = dir ? bb : bf;
    float* out        = dir ? g_gi_b : g_gi_f;
    int t0 = blockIdx.x * TT;
    int r0 = blockIdx.y * RR;

    __shared__ float Xs[TT][KC];
    __shared__ float Ws[RR][KC + 1];

    int tid = threadIdx.x;
    int r  = tid % RR;
    int tg = tid / RR;

    float acc[8];
    #pragma unroll
    for (int j = 0; j < 8; ++j) acc[j] = 0.f;

    for (int kk = 0; kk < E; kk += KC) {
        for (int i = tid; i < RR * KC; i += 256) {
            int rr = i / KC, k = i % KC;
            Ws[rr][k] = (kk + k < E) ? W[(r0 + rr) * E + kk + k] : 0.f;
        }
        for (int i = tid; i < TT * KC; i += 256) {
            int ttl = i / KC, k = i % KC;
            int t = t0 + ttl;
            float v = 0.f;
            if (t < S && kk + k < E) {
                int tsrc = dir ? (S - 1 - t) : t;
                v = g_X[tsrc * E + kk + k];
            }
            Xs[ttl][k] = v;
        }
        __syncthreads();
        #pragma unroll
        for (int k = 0; k < KC; ++k) {
            float wv = Ws[r][k];
            #pragma unroll
            for (int j = 0; j < 8; ++j)
                acc[j] += wv * Xs[tg * 8 + j][k];
        }
        __syncthreads();
    }
    float bv = bias[r0 + r];
    #pragma unroll
    for (int j = 0; j < 8; ++j) {
        int t = t0 + tg * 8 + j;
        if (t < S) out[t * G3 + r0 + r] = acc[j] + bv;
    }
}

// ---------------- kernel 3: GRU recurrence, cluster(8) per direction ----------
// R13 protocol; dot reshaped for a SHALLOW reduce:
// warp w owns local rows 8w..8w+7. Lane group g = lane>>3 (4 groups of 8),
// sub = lane&7. Lane handles rows rA = 8w+g, rB = 8w+4+g over cols
// sub*32..sub*32+31 (16 f32x2 each; 4 independent accumulator chains per row).
// Reduce: fold rA/rB at xor4, then xor1+xor2 -> 3 dependent shuffles (~78 cyc
// vs 130 for the 5-level tree). Lanes with (lane&3)==0 STS row sums (+bias).
// Funnel identical to R13 (bar split, HW tanh gates, 8 DSMEM stores + 8 plain
// arrives). Double-buffered h + parity.
__global__ void __launch_bounds__(GRU_T, 1) __cluster_dims__(NC, 1, 1)
gru_kernel(const float* __restrict__ Whh_f, const float* __restrict__ bhh_f,
           const float* __restrict__ Whh_b, const float* __restrict__ bhh_b) {
    int dir = blockIdx.x >> 3;
    unsigned c = cluster_rank();
    const float* Whh = dir ? Whh_b : Whh_f;
    const float* bhh = dir ? bhh_b : bhh_f;
    const float* gi  = dir ? g_gi_b : g_gi_f;
    float* ys        = dir ? g_ys_b : g_ys_f;

    int tid  = threadIdx.x;
    int w    = tid >> 5;        // 0..11
    int lane = tid & 31;
    int base = (int)c * DPC;
    int g    = lane >> 3;       // row group 0..3
    int sub  = lane & 7;        // column octet position

    __shared__ __align__(16) float hbuf[2][H];   // double-buffered full h
    __shared__ float s_gh[96];                   // row sums incl. bhh
    __shared__ __align__(8) unsigned long long bars[2];

    unsigned hbuf_u32 = smem_u32(&hbuf[0][0]);
    unsigned bars_u32 = smem_u32(&bars[0]);

    if (tid == 0) { mbar_init(bars_u32, NC); mbar_init(bars_u32 + 8, NC); }
    if (tid < H) hbuf[0][tid] = 0.f;
    __syncthreads();
    cluster_sync();   // peers must not arrive on an uninitialized mbarrier

    // precomputed remote addresses (used by warp 0)
    unsigned remh[NC], remb[NC];
    #pragma unroll
    for (int r = 0; r < NC; ++r) {
        remh[r] = mapa_u32(hbuf_u32, (unsigned)r);
        remb[r] = mapa_u32(bars_u32, (unsigned)r);
    }

    // resident weights: rows rA=8w+g and rB=8w+4+g, cols sub*32..+32 (f32x2)
    unsigned long long wA[16], wB[16];
    {
        int lrA = w * 8 + g;
        int lrB = w * 8 + 4 + g;
        int rowA = (lrA >> 5) * H + base + (lrA & 31);
        int rowB = (lrB >> 5) * H + base + (lrB & 31);
        const float* pa = Whh + (size_t)rowA * H + sub * 32;
        const float* pb = Whh + (size_t)rowB * H + sub * 32;
        #pragma unroll
        for (int q = 0; q < 8; ++q) {
            float4 a = *(const float4*)(pa + q * 4);
            float4 b = *(const float4*)(pb + q * 4);
            wA[q * 2]     = pk2(a.x, a.y); wA[q * 2 + 1] = pk2(a.z, a.w);
            wB[q * 2]     = pk2(b.x, b.y); wB[q * 2 + 1] = pk2(b.z, b.w);
        }
    }
    // bias for the row slot this lane owns after the fold reduce:
    // slot = w*8 + g + 4*((lane>>2)&1)
    float breg;
    {
        int slot = w * 8 + g + 4 * ((lane >> 2) & 1);
        int rowb = ((slot & 7) >= 4 ? ((w * 8 + 4 + g)) : (w * 8 + g));
        rowb = (rowb >> 5) * H + base + (rowb & 31);
        // note: slot&7 - layout: slot row index within warp = g + 4*bit
        breg = bhh[rowb];
    }

    // warp0 per-lane gate state (lane = local dim)
    float gir = 0.f, giz = 0.f, gin = 0.f, hold = 0.f;
    if (w == 0) {
        int ii = base + lane;
        gir = gi[ii]; giz = gi[H + ii]; gin = gi[2 * H + ii];   // step 0
    }

    unsigned ph0 = 0, ph1 = 0;
    const unsigned FM = 0xffffffffu;

    for (int t = 0; t < S; ++t) {
        // prefetch gi for step t+1 (warp 0 only; hidden under dot+wait)
        float ngr = 0.f, ngz = 0.f, ngn = 0.f;
        if (w == 0 && t + 1 < S) {
            const float* gp = gi + (t + 1) * G3 + base + lane;
            ngr = __ldg(gp); ngz = __ldg(gp + H); ngn = __ldg(gp + 2 * H);
        }

        // wait for h_t in hbuf[t&1]; t=0 uses zeros
        if (t) {
            if (t & 1) { mbar_wait_cluster(bars_u32 + 8, ph1); ph1 ^= 1; }
            else       { mbar_wait_cluster(bars_u32,     ph0); ph0 ^= 1; }
        }

        // h slice for this lane: 32 floats = 16 f32x2 (broadcast across octets)
        const ulonglong2* hp =
            (const ulonglong2*)(&hbuf[t & 1][sub * 32]);
        unsigned long long h2[16];
        #pragma unroll
        for (int q = 0; q < 8; ++q) {
            ulonglong2 hv = hp[q];
            h2[q * 2] = hv.x; h2[q * 2 + 1] = hv.y;
        }

        // dot: 2 rows x 32 cols; 4 independent chains of 4 ffma2 per row
        float pA, pB;
        {
            unsigned long long a0 = ffma2(wA[0], h2[0], 0ULL);
            unsigned long long a1 = ffma2(wA[1], h2[1], 0ULL);
            unsigned long long a2 = ffma2(wA[2], h2[2], 0ULL);
            unsigned long long a3 = ffma2(wA[3], h2[3], 0ULL);
            #pragma unroll
            for (int q = 1; q < 4; ++q) {
                a0 = ffma2(wA[q * 4],     h2[q * 4],     a0);
                a1 = ffma2(wA[q * 4 + 1], h2[q * 4 + 1], a1);
                a2 = ffma2(wA[q * 4 + 2], h2[q * 4 + 2], a2);
                a3 = ffma2(wA[q * 4 + 3], h2[q * 4 + 3], a3);
            }
            pA = unpk_sum(fadd2(fadd2(a0, a1), fadd2(a2, a3)));
        }
        {
            unsigned long long b0v = ffma2(wB[0], h2[0], 0ULL);
            unsigned long long b1v = ffma2(wB[1], h2[1], 0ULL);
            unsigned long long b2v = ffma2(wB[2], h2[2], 0ULL);
            unsigned long long b3v = ffma2(wB[3], h2[3], 0ULL);
            #pragma unroll
            for (int q = 1; q < 4; ++q) {
                b0v = ffma2(wB[q * 4],     h2[q * 4],     b0v);
                b1v = ffma2(wB[q * 4 + 1], h2[q * 4 + 1], b1v);
                b2v = ffma2(wB[q * 4 + 2], h2[q * 4 + 2], b2v);
                b3v = ffma2(wB[q * 4 + 3], h2[q * 4 + 3], b3v);
            }
            pB = unpk_sum(fadd2(fadd2(b0v, b1v), fadd2(b2v, b3v)));
        }

        // shallow reduce: fold rA/rB at xor4, then finish with xor1 + xor2
        bool bit2 = (lane & 4);
        float u;
        { float v = bit2 ? pA : pB;
          float sx = __shfl_xor_sync(FM, v, 4);
          u = (bit2 ? pB : pA) + sx; }
        u += __shfl_xor_sync(FM, u, 1);
        u += __shfl_xor_sync(FM, u, 2);
        // lanes with (lane&3)==0 hold full sums: lane 8g -> row 8w+g,
        // lane 8g+4 -> row 8w+4+g
        if ((lane & 3) == 0) {
            int slot = w * 8 + g + 4 * ((lane >> 2) & 1);
            s_gh[slot] = u + breg;
        }

        if (w != 0) {
            bar_arrive_1();        // non-blocking; next stop: mbar wait t+1
        } else {
            bar_sync_1();          // wait for all 12 warps' STS (BAR drains STS)
            // gates: lane = local dim — HW tanh.approx path
            float ghr = s_gh[lane];
            float ghz = s_gh[32 + lane];
            float ghn = s_gh[64 + lane];
            float rr = fsigmoid_hw(gir + ghr);
            float zz = fsigmoid_hw(giz + ghz);
            float nn = tanh_hw(fmaf(rr, ghn, gin));
            float hn = (1.f - zz) * nn + zz * hold;
            hold = hn;

            // publish h_{t+1} to all 8 CTAs (register-direct DSMEM stores)
            if (t + 1 < S) {
                unsigned off = (unsigned)(((t + 1) & 1) * (H * 4) + (base + lane) * 4);
                #pragma unroll
                for (int r = 0; r < NC; ++r)
                    st_cluster_f32(remh[r] + off, hn);
                __syncwarp();
                if (lane < NC)
                    mbar_arrive_remote(remb[lane] + ((t + 1) & 1) * 8);
            }

            int trow = dir ? (S - 1 - t) : t;
            ys[trow * H + base + lane] = hn;
            gir = ngr; giz = ngz; gin = ngn;
        }
    }
    cluster_sync();
}

// ---------------- kernel 4: output projection --------------------------------
#define OTT 16
__global__ void outproj_kernel(const float* __restrict__ Wl,
                               const float* __restrict__ bl,
                               float* __restrict__ outbuf) {
    int t0 = blockIdx.x * OTT;
    int j0 = blockIdx.y * RR;
    __shared__ float As[OTT][KC];
    __shared__ float Ws[RR][KC + 1];
    int tid = threadIdx.x;
    int r  = tid % RR;
    int tg = tid / RR;
    float acc[4];
    #pragma unroll
    for (int j = 0; j < 4; ++j) acc[j] = 0.f;

    for (int kk = 0; kk < 2 * H; kk += KC) {
        const float* ysrc = (kk < H) ? g_ys_f : g_ys_b;
        int kbase = (kk < H) ? kk : (kk - H);
        for (int i = tid; i < RR * KC; i += 256) {
            int rr = i / KC, k = i % KC;
            Ws[rr][k] = Wl[(j0 + rr) * (2 * H) + kk + k];
        }
        for (int i = tid; i < OTT * KC; i += 256) {
            int ttl = i / KC, k = i % KC;
            int t = t0 + ttl;
            As[ttl][k] = (t < S) ? ysrc[t * H + kbase + k] : 0.f;
        }
        __syncthreads();
        #pragma unroll
        for (int k = 0; k < KC; ++k) {
            float wv = Ws[r][k];
            #pragma unroll
            for (int j = 0; j < 4; ++j)
                acc[j] += wv * As[tg * 4 + j][k];
        }
        __syncthreads();
    }
    float bv = bl[j0 + r];
    #pragma unroll
    for (int j = 0; j < 4; ++j) {
        int t = t0 + tg * 4 + j;
        if (t < S) outbuf[t * H + j0 + r] = acc[j] + bv;
    }
}

// ---------------- kernel 5: attention + final head (single block) -------------
__global__ void attn_kernel(const float* __restrict__ outbuf,
                            const float* __restrict__ Wo,
                            const float* __restrict__ bo,
                            const float* __restrict__ label,
                            float* __restrict__ tail) {
    __shared__ float s_hsum[H];
    __shared__ float s_w[S];
    __shared__ float s_red[32];
    __shared__ float s_ctx[4][H];

    int tid = threadIdx.x;
    int wp  = tid >> 5;
    int ln  = tid & 31;

    if (tid < H) s_hsum[tid] = g_ys_f[(S - 1) * H + tid] + g_ys_b[tid];
    __syncthreads();

    for (int t = wp; t < S; t += 32) {
        const float* o = outbuf + t * H;
        float s = 0.f;
        #pragma unroll
        for (int k = ln; k < H; k += 32) s += o[k] * s_hsum[k];
        s += __shfl_down_sync(0xffffffffu, s, 16);
        s += __shfl_down_sync(0xffffffffu, s, 8);
        s += __shfl_down_sync(0xffffffffu, s, 4);
        s += __shfl_down_sync(0xffffffffu, s, 2);
        s += __shfl_down_sync(0xffffffffu, s, 1);
        if (ln == 0) s_w[t] = s;
    }
    __syncthreads();

    float m = -CUDART_INF_F;
    for (int t = tid; t < S; t += 1024) m = fmaxf(m, s_w[t]);
    for (int off = 16; off >= 1; off >>= 1)
        m = fmaxf(m, __shfl_down_sync(0xffffffffu, m, off));
    if (ln == 0) s_red[wp] = m;
    __syncthreads();
    if (tid < 32) {
        float mm = s_red[tid];
        for (int off = 16; off >= 1; off >>= 1)
            mm = fmaxf(mm, __shfl_down_sync(0xffffffffu, mm, off));
        if (tid == 0) s_red[0] = mm;
    }
    __syncthreads();
    float M = s_red[0];
    __syncthreads();

    float lsum = 0.f;
    for (int t = tid; t < S; t += 1024) {
        float e = expf(s_w[t] - M);
        s_w[t] = e;
        lsum += e;
    }
    for (int off = 16; off >= 1; off >>= 1)
        lsum += __shfl_down_sync(0xffffffffu, lsum, off);
    if (ln == 0) s_red[wp] = lsum;
    __syncthreads();
    if (tid < 32) {
        float ss = s_red[tid];
        for (int off = 16; off >= 1; off >>= 1)
            ss += __shfl_down_sync(0xffffffffu, ss, off);
        if (tid == 0) s_red[0] = ss;
    }
    __syncthreads();
    float SUM = s_red[0];

    int j    = tid & 255;
    int part = tid >> 8;
    float cacc = 0.f;
    #pragma unroll 4
    for (int t = part; t < S; t += 4) cacc += s_w[t] * outbuf[t * H + j];
    s_ctx[part][j] = cacc;
    __syncthreads();

    if (tid < H) {
        float cj = (s_ctx[0][tid] + s_ctx[1][tid] + s_ctx[2][tid] + s_ctx[3][tid]) / SUM;
        s_hsum[tid] = cj * Wo[tid];
    }
    __syncthreads();

    if (tid < 32) {
        float a = 0.f;
        #pragma unroll
        for (int q = 0; q < 8; ++q) a += s_hsum[tid + q * 32];
        for (int off = 16; off >= 1; off >>= 1)
            a += __shfl_down_sync(0xffffffffu, a, off);
        if (tid == 0) {
            float res = 1.f / (1.f + expf(-(a + bo[0])));
            float d = label[0] - res;
            tail[0] = d * d;
            tail[1] = res;
        }
    }
}

// ---------------- launch ------------------------------------------------------
extern "C" void kernel_launch(void* const* d_in, const int* in_sizes, int n_in,
                              void* d_out, int out_size) {
    const int*   orig   = (const int*)d_in[0];
    const int*   reply  = (const int*)d_in[1];
    const int*   lens   = (const int*)d_in[2];
    const float* label  = (const float*)d_in[3];
    const float* embed  = (const float*)d_in[4];
    const float* Wih_f  = (const float*)d_in[5];
    const float* Whh_f  = (const float*)d_in[6];
    const float* bih_f  = (const float*)d_in[7];
    const float* bhh_f  = (const float*)d_in[8];
    const float* Wih_b  = (const float*)d_in[9];
    const float* Whh_b  = (const float*)d_in[10];
    const float* bih_b  = (const float*)d_in[11];
    const float* bhh_b  = (const float*)d_in[12];
    const float* Wl     = (const float*)d_in[13];
    const float* bl     = (const float*)d_in[14];
    const float* Wo     = (const float*)d_in[15];
    const float* bo     = (const float*)d_in[16];
    float* out = (float*)d_out;

    embed_kernel<<<S, 320>>>(orig, reply, lens, embed);

    dim3 gi_grid((S + TT - 1) / TT, G3 / RR, 2);
    gi_kernel<<<gi_grid, 256>>>(Wih_f, bih_f, Wih_b, bih_b);

    gru_kernel<<<2 * NC, GRU_T>>>(Whh_f, bhh_f, Whh_b, bhh_b);

    dim3 op_grid((S + OTT - 1) / OTT, H / RR);   // 129 x 4
    outproj_kernel<<<op_grid, 256>>>(Wl, bl, out);

    attn_kernel<<<1, 1024>>>(out, Wo, bo, label, out + S * H);
}

// round 15
// speedup vs baseline: 2.7970x; 2.7970x over previous
#include <cuda_runtime.h>
#include <math_constants.h>

#define V  50000
#define E  300
#define H  256
#define R  2048
#define L0 128
#define LR 64
#define S  2049          // 1 + R
#define G3 768           // 3*H

#define NC     8         // CTAs per cluster (one cluster per direction)
#define DPC    32        // h-dims per CTA
#define GRU_T  384       // 12 warps x 8 rows = 96 rows per CTA

// ---------------- scratch (device globals; no allocation allowed) -------------
__device__ float g_X[S * E];
__device__ float g_gi_f[S * G3];
__device__ float g_gi_b[S * G3];
__device__ float g_ys_f[S * H];
__device__ float g_ys_b[S * H];

// ---------------- small PTX helpers ------------------------------------------
__device__ __forceinline__ unsigned long long pk2(float lo, float hi) {
    unsigned long long r;
    asm("mov.b64 %0, {%1, %2};" : "=l"(r) : "f"(lo), "f"(hi));
    return r;
}
__device__ __forceinline__ float unpk_sum(unsigned long long v) {
    float a, b;
    asm("mov.b64 {%0, %1}, %2;" : "=f"(a), "=f"(b) : "l"(v));
    return a + b;
}
__device__ __forceinline__ unsigned long long ffma2(unsigned long long a,
                                                    unsigned long long b,
                                                    unsigned long long c) {
    unsigned long long d;
    asm("fma.rn.f32x2 %0, %1, %2, %3;" : "=l"(d) : "l"(a), "l"(b), "l"(c));
    return d;
}
__device__ __forceinline__ unsigned smem_u32(const void* p) {
    return (unsigned)__cvta_generic_to_shared(p);
}
__device__ __forceinline__ void mbar_init(unsigned addr, unsigned count) {
    asm volatile("mbarrier.init.shared.b64 [%0], %1;" :: "r"(addr), "r"(count) : "memory");
}
__device__ __forceinline__ void mbar_wait_cluster(unsigned addr, unsigned parity) {
    unsigned done;
    do {
        asm volatile(
            "{\n\t.reg .pred p;\n\t"
            "mbarrier.try_wait.parity.acquire.cluster.shared::cta.b64 p, [%1], %2, 0x989680;\n\t"
            "selp.b32 %0, 1, 0, p;\n\t}"
            : "=r"(done) : "r"(addr), "r"(parity) : "memory");
    } while (!done);
}
__device__ __forceinline__ unsigned cluster_rank() {
    unsigned r;
    asm("mov.u32 %0, %%cluster_ctarank;" : "=r"(r));
    return r;
}
__device__ __forceinline__ unsigned mapa_u32(unsigned addr, unsigned rank) {
    unsigned rem;
    asm("mapa.shared::cluster.u32 %0, %1, %2;" : "=r"(rem) : "r"(addr), "r"(rank));
    return rem;
}
__device__ __forceinline__ void st_cluster_f32(unsigned addr, float v) {
    asm volatile("st.shared::cluster.f32 [%0], %1;" :: "r"(addr), "f"(v) : "memory");
}
// plain (non-release) remote arrive — the R4-verified fast path
__device__ __forceinline__ void mbar_arrive_remote(unsigned addr) {
    asm volatile("mbarrier.arrive.shared::cluster.b64 _, [%0];" :: "r"(addr) : "memory");
}
__device__ __forceinline__ void cluster_sync() {
    asm volatile("barrier.cluster.arrive.aligned;" ::: "memory");
    asm volatile("barrier.cluster.wait.aligned;" ::: "memory");
}
__device__ __forceinline__ void bar_arrive_1() {
    asm volatile("bar.arrive 1, %0;" :: "r"(GRU_T) : "memory");
}
__device__ __forceinline__ void bar_sync_1() {
    asm volatile("bar.sync 1, %0;" :: "r"(GRU_T) : "memory");
}
// HW tanh (sm_75+): single special-function op, ~16 cyc
__device__ __forceinline__ float tanh_hw(float x) {
    float y;
    asm("tanh.approx.f32 %0, %1;" : "=f"(y) : "f"(x));
    return y;
}
// sigmoid via HW tanh: sigmoid(x) = 0.5*tanh(x/2) + 0.5
__device__ __forceinline__ float fsigmoid_hw(float x) {
    return fmaf(0.5f, tanh_hw(0.5f * x), 0.5f);
}

// ---------------- kernel 1: embedding sums -> X -------------------------------
__global__ void embed_kernel(const int* __restrict__ orig,
                             const int* __restrict__ reply,
                             const int* __restrict__ lens,
                             const float* __restrict__ embed) {
    int t = blockIdx.x;
    int e = threadIdx.x;
    if (e >= E) return;
    float acc = 0.f;
    if (t == 0) {
        #pragma unroll 4
        for (int l = 0; l < L0; ++l) {
            int tok = orig[l];
            acc += embed[(long long)tok * E + e];
        }
    } else {
        int r = t - 1;
        int len = lens[r];
        const int* rt = reply + r * LR;
        #pragma unroll 4
        for (int l = 0; l < len; ++l) {
            int tok = rt[l];
            acc += embed[(long long)tok * E + e];
        }
    }
    g_X[t * E + e] = acc;
}

// ---------------- kernel 2: gi GEMMs (both directions) ------------------------
#define TT 32
#define RR 64
#define KC 32
__global__ void gi_kernel(const float* __restrict__ Wf, const float* __restrict__ bf,
                          const float* __restrict__ Wb, const float* __restrict__ bb) {
    int dir = blockIdx.z;
    const float* W    = dir ? Wb : Wf;
    const float* bias = dir ? bb : bf;
    float* out        = dir ? g_gi_b : g_gi_f;
    int t0 = blockIdx.x * TT;
    int r0 = blockIdx.y * RR;

    __shared__ float Xs[TT][KC];
    __shared__ float Ws[RR][KC + 1];

    int tid = threadIdx.x;
    int r  = tid % RR;
    int tg = tid / RR;

    float acc[8];
    #pragma unroll
    for (int j = 0; j < 8; ++j) acc[j] = 0.f;

    for (int kk = 0; kk < E; kk += KC) {
        for (int i = tid; i < RR * KC; i += 256) {
            int rr = i / KC, k = i % KC;
            Ws[rr][k] = (kk + k < E) ? W[(r0 + rr) * E + kk + k] : 0.f;
        }
        for (int i = tid; i < TT * KC; i += 256) {
            int ttl = i / KC, k = i % KC;
            int t = t0 + ttl;
            float v = 0.f;
            if (t < S && kk + k < E) {
                int tsrc = dir ? (S - 1 - t) : t;
                v = g_X[tsrc * E + kk + k];
            }
            Xs[ttl][k] = v;
        }
        __syncthreads();
        #pragma unroll
        for (int k = 0; k < KC; ++k) {
            float wv = Ws[r][k];
            #pragma unroll
            for (int j = 0; j < 8; ++j)
                acc[j] += wv * Xs[tg * 8 + j][k];
        }
        __syncthreads();
    }
    float bv = bias[r0 + r];
    #pragma unroll
    for (int j = 0; j < 8; ++j) {
        int t = t0 + tg * 8 + j;
        if (t < S) out[t * G3 + r0 + r] = acc[j] + bv;
    }
}

// ---------------- kernel 3: GRU recurrence, cluster(8) per direction ----------
// R13 structure (verified 1491us) with a TRUNCATED reduce tree:
// the fold stops after the xor4 level (depth 3, ~78 cyc vs ~130). At that
// point lane l holds the partial of row 8w+(l&7) summed over its aligned
// 8-lane octet (cols (l>>3)*64..+64). ALL 32 lanes STS their partial into
// s_gh4[96][4] (flat index w*32+(l&7)*4+(l>>3): a 0..31 permutation ->
// conflict-free). The warp-0 funnel sums 4 partials per gate row with one
// LDS.128 + depth-2 FADD. Everything else (mbar protocol, HW tanh gates,
// 8 DSMEM stores + 8 plain arrives) identical to R13.
__global__ void __launch_bounds__(GRU_T, 1) __cluster_dims__(NC, 1, 1)
gru_kernel(const float* __restrict__ Whh_f, const float* __restrict__ bhh_f,
           const float* __restrict__ Whh_b, const float* __restrict__ bhh_b) {
    int dir = blockIdx.x >> 3;
    unsigned c = cluster_rank();
    const float* Whh = dir ? Whh_b : Whh_f;
    const float* bhh = dir ? bhh_b : bhh_f;
    const float* gi  = dir ? g_gi_b : g_gi_f;
    float* ys        = dir ? g_ys_b : g_ys_f;

    int tid  = threadIdx.x;
    int w    = tid >> 5;        // 0..11
    int lane = tid & 31;
    int base = (int)c * DPC;

    __shared__ __align__(16) float hbuf[2][H];   // double-buffered full h
    __shared__ __align__(16) float4 s_gh4[96];   // per-row octet partials
    __shared__ __align__(8) unsigned long long bars[2];

    unsigned hbuf_u32 = smem_u32(&hbuf[0][0]);
    unsigned bars_u32 = smem_u32(&bars[0]);

    if (tid == 0) { mbar_init(bars_u32, NC); mbar_init(bars_u32 + 8, NC); }
    if (tid < H) hbuf[0][tid] = 0.f;
    __syncthreads();
    cluster_sync();   // peers must not arrive on an uninitialized mbarrier

    // precomputed remote addresses (used by warp 0)
    unsigned remh[NC], remb[NC];
    #pragma unroll
    for (int r = 0; r < NC; ++r) {
        remh[r] = mapa_u32(hbuf_u32, (unsigned)r);
        remb[r] = mapa_u32(bars_u32, (unsigned)r);
    }

    // resident weights: 8 rows x 8 cols per lane, packed f32x2
    unsigned long long w2[8][4];
    #pragma unroll
    for (int k = 0; k < 8; ++k) {
        int lr = w * 8 + k;
        int row = (lr >> 5) * H + base + (lr & 31);
        const float* wr = Whh + (size_t)row * H + lane * 8;
        float4 a = *(const float4*)wr;
        float4 b = *(const float4*)(wr + 4);
        w2[k][0] = pk2(a.x, a.y); w2[k][1] = pk2(a.z, a.w);
        w2[k][2] = pk2(b.x, b.y); w2[k][3] = pk2(b.z, b.w);
    }
    // bias for the row slot this lane's fold value belongs to (row 8w+(lane&7));
    // added only by the part-0 octet (lanes 0-7) to avoid double counting.
    float breg;
    {
        int lrb = w * 8 + (lane & 7);
        int rowb = (lrb >> 5) * H + base + (lrb & 31);
        breg = (lane < 8) ? bhh[rowb] : 0.f;
    }
    // flat STS index for this lane's partial (permutation of 0..31 per warp)
    unsigned gh_sts = smem_u32(&s_gh4[0]) +
        (unsigned)((w * 32 + (lane & 7) * 4 + (lane >> 3)) * 4);

    // warp0 per-lane gate state (lane = local dim)
    float gir = 0.f, giz = 0.f, gin = 0.f, hold = 0.f;
    if (w == 0) {
        int ii = base + lane;
        gir = gi[ii]; giz = gi[H + ii]; gin = gi[2 * H + ii];   // step 0
    }

    unsigned ph0 = 0, ph1 = 0;
    const unsigned FM = 0xffffffffu;

    for (int t = 0; t < S; ++t) {
        // prefetch gi for step t+1 (warp 0 only; hidden under dot+wait)
        float ngr = 0.f, ngz = 0.f, ngn = 0.f;
        if (w == 0 && t + 1 < S) {
            const float* gp = gi + (t + 1) * G3 + base + lane;
            ngr = __ldg(gp); ngz = __ldg(gp + H); ngn = __ldg(gp + 2 * H);
        }

        // wait for h_t in hbuf[t&1]; t=0 uses zeros
        if (t) {
            if (t & 1) { mbar_wait_cluster(bars_u32 + 8, ph1); ph1 ^= 1; }
            else       { mbar_wait_cluster(bars_u32,     ph0); ph0 ^= 1; }
        }

        // dot: 8 rows x 8 cols per lane; h loaded directly as f32x2 pairs
        const ulonglong2* hp =
            (const ulonglong2*)(&hbuf[t & 1][lane * 8]);
        ulonglong2 ha = hp[0];
        ulonglong2 hb = hp[1];
        unsigned long long h2[4];
        h2[0] = ha.x; h2[1] = ha.y; h2[2] = hb.x; h2[3] = hb.y;

        float p[8];
        #pragma unroll
        for (int k = 0; k < 8; ++k) {
            unsigned long long acc = ffma2(w2[k][0], h2[0], 0ULL);
            acc = ffma2(w2[k][1], h2[1], acc);
            acc = ffma2(w2[k][2], h2[2], acc);
            acc = ffma2(w2[k][3], h2[3], acc);
            p[k] = unpk_sum(acc);
        }

        // fold reduce TRUNCATED at depth 3: u = octet partial of row 8w+(lane&7)
        bool b0 = (lane & 1), b1 = (lane & 2), b2 = (lane & 4);
        float q0, q1, q2, q3, r0v, r1v, u;
        { float v = b0 ? p[0] : p[1]; float sx = __shfl_xor_sync(FM, v, 1);
          q0 = (b0 ? p[1] : p[0]) + sx; }
        { float v = b0 ? p[2] : p[3]; float sx = __shfl_xor_sync(FM, v, 1);
          q1 = (b0 ? p[3] : p[2]) + sx; }
        { float v = b0 ? p[4] : p[5]; float sx = __shfl_xor_sync(FM, v, 1);
          q2 = (b0 ? p[5] : p[4]) + sx; }
        { float v = b0 ? p[6] : p[7]; float sx = __shfl_xor_sync(FM, v, 1);
          q3 = (b0 ? p[7] : p[6]) + sx; }
        { float v = b1 ? q0 : q1; float sx = __shfl_xor_sync(FM, v, 2);
          r0v = (b1 ? q1 : q0) + sx; }
        { float v = b1 ? q2 : q3; float sx = __shfl_xor_sync(FM, v, 2);
          r1v = (b1 ? q3 : q2) + sx; }
        { float v = b2 ? r0v : r1v; float sx = __shfl_xor_sync(FM, v, 4);
          u = (b2 ? r1v : r0v) + sx; }
        // all 32 lanes store their octet partial (+bias in part 0)
        asm volatile("st.shared.f32 [%0], %1;" :: "r"(gh_sts), "f"(u + breg) : "memory");

        if (w != 0) {
            bar_arrive_1();        // non-blocking; next stop: mbar wait t+1
        } else {
            bar_sync_1();          // wait for all 12 warps' STS (BAR drains STS)
            // gates: lane = local dim; sum 4 octet partials per row (LDS.128)
            float4 vr = s_gh4[lane];
            float4 vz = s_gh4[32 + lane];
            float4 vn = s_gh4[64 + lane];
            float ghr = (vr.x + vr.y) + (vr.z + vr.w);
            float ghz = (vz.x + vz.y) + (vz.z + vz.w);
            float ghn = (vn.x + vn.y) + (vn.z + vn.w);
            float rr = fsigmoid_hw(gir + ghr);
            float zz = fsigmoid_hw(giz + ghz);
            float nn = tanh_hw(fmaf(rr, ghn, gin));
            float hn = fmaf(zz, hold - nn, nn);
            hold = hn;

            // publish h_{t+1} to all 8 CTAs (register-direct DSMEM stores)
            if (t + 1 < S) {
                unsigned off = (unsigned)(((t + 1) & 1) * (H * 4) + (base + lane) * 4);
                #pragma unroll
                for (int r = 0; r < NC; ++r)
                    st_cluster_f32(remh[r] + off, hn);
                __syncwarp();
                if (lane < NC)
                    mbar_arrive_remote(remb[lane] + ((t + 1) & 1) * 8);
            }

            int trow = dir ? (S - 1 - t) : t;
            ys[trow * H + base + lane] = hn;
            gir = ngr; giz = ngz; gin = ngn;
        }
    }
    cluster_sync();
}

// ---------------- kernel 4: output projection --------------------------------
#define OTT 16
__global__ void outproj_kernel(const float* __restrict__ Wl,
                               const float* __restrict__ bl,
                               float* __restrict__ outbuf) {
    int t0 = blockIdx.x * OTT;
    int j0 = blockIdx.y * RR;
    __shared__ float As[OTT][KC];
    __shared__ float Ws[RR][KC + 1];
    int tid = threadIdx.x;
    int r  = tid % RR;
    int tg = tid / RR;
    float acc[4];
    #pragma unroll
    for (int j = 0; j < 4; ++j) acc[j] = 0.f;

    for (int kk = 0; kk < 2 * H; kk += KC) {
        const float* ysrc = (kk < H) ? g_ys_f : g_ys_b;
        int kbase = (kk < H) ? kk : (kk - H);
        for (int i = tid; i < RR * KC; i += 256) {
            int rr = i / KC, k = i % KC;
            Ws[rr][k] = Wl[(j0 + rr) * (2 * H) + kk + k];
        }
        for (int i = tid; i < OTT * KC; i += 256) {
            int ttl = i / KC, k = i % KC;
            int t = t0 + ttl;
            As[ttl][k] = (t < S) ? ysrc[t * H + kbase + k] : 0.f;
        }
        __syncthreads();
        #pragma unroll
        for (int k = 0; k < KC; ++k) {
            float wv = Ws[r][k];
            #pragma unroll
            for (int j = 0; j < 4; ++j)
                acc[j] += wv * As[tg * 4 + j][k];
        }
        __syncthreads();
    }
    float bv = bl[j0 + r];
    #pragma unroll
    for (int j = 0; j < 4; ++j) {
        int t = t0 + tg * 4 + j;
        if (t < S) outbuf[t * H + j0 + r] = acc[j] + bv;
    }
}

// ---------------- kernel 5: attention + final head (single block) -------------
__global__ void attn_kernel(const float* __restrict__ outbuf,
                            const float* __restrict__ Wo,
                            const float* __restrict__ bo,
                            const float* __restrict__ label,
                            float* __restrict__ tail) {
    __shared__ float s_hsum[H];
    __shared__ float s_w[S];
    __shared__ float s_red[32];
    __shared__ float s_ctx[4][H];

    int tid = threadIdx.x;
    int wp  = tid >> 5;
    int ln  = tid & 31;

    if (tid < H) s_hsum[tid] = g_ys_f[(S - 1) * H + tid] + g_ys_b[tid];
    __syncthreads();

    for (int t = wp; t < S; t += 32) {
        const float* o = outbuf + t * H;
        float s = 0.f;
        #pragma unroll
        for (int k = ln; k < H; k += 32) s += o[k] * s_hsum[k];
        s += __shfl_down_sync(0xffffffffu, s, 16);
        s += __shfl_down_sync(0xffffffffu, s, 8);
        s += __shfl_down_sync(0xffffffffu, s, 4);
        s += __shfl_down_sync(0xffffffffu, s, 2);
        s += __shfl_down_sync(0xffffffffu, s, 1);
        if (ln == 0) s_w[t] = s;
    }
    __syncthreads();

    float m = -CUDART_INF_F;
    for (int t = tid; t < S; t += 1024) m = fmaxf(m, s_w[t]);
    for (int off = 16; off >= 1; off >>= 1)
        m = fmaxf(m, __shfl_down_sync(0xffffffffu, m, off));
    if (ln == 0) s_red[wp] = m;
    __syncthreads();
    if (tid < 32) {
        float mm = s_red[tid];
        for (int off = 16; off >= 1; off >>= 1)
            mm = fmaxf(mm, __shfl_down_sync(0xffffffffu, mm, off));
        if (tid == 0) s_red[0] = mm;
    }
    __syncthreads();
    float M = s_red[0];
    __syncthreads();

    float lsum = 0.f;
    for (int t = tid; t < S; t += 1024) {
        float e = expf(s_w[t] - M);
        s_w[t] = e;
        lsum += e;
    }
    for (int off = 16; off >= 1; off >>= 1)
        lsum += __shfl_down_sync(0xffffffffu, lsum, off);
    if (ln == 0) s_red[wp] = lsum;
    __syncthreads();
    if (tid < 32) {
        float ss = s_red[tid];
        for (int off = 16; off >= 1; off >>= 1)
            ss += __shfl_down_sync(0xffffffffu, ss, off);
        if (tid == 0) s_red[0] = ss;
    }
    __syncthreads();
    float SUM = s_red[0];

    int j    = tid & 255;
    int part = tid >> 8;
    float cacc = 0.f;
    #pragma unroll 4
    for (int t = part; t < S; t += 4) cacc += s_w[t] * outbuf[t * H + j];
    s_ctx[part][j] = cacc;
    __syncthreads();

    if (tid < H) {
        float cj = (s_ctx[0][tid] + s_ctx[1][tid] + s_ctx[2][tid] + s_ctx[3][tid]) / SUM;
        s_hsum[tid] = cj * Wo[tid];
    }
    __syncthreads();

    if (tid < 32) {
        float a = 0.f;
        #pragma unroll
        for (int q = 0; q < 8; ++q) a += s_hsum[tid + q * 32];
        for (int off = 16; off >= 1; off >>= 1)
            a += __shfl_down_sync(0xffffffffu, a, off);
        if (tid == 0) {
            float res = 1.f / (1.f + expf(-(a + bo[0])));
            float d = label[0] - res;
            tail[0] = d * d;
            tail[1] = res;
        }
    }
}

// ---------------- launch ------------------------------------------------------
extern "C" void kernel_launch(void* const* d_in, const int* in_sizes, int n_in,
                              void* d_out, int out_size) {
    const int*   orig   = (const int*)d_in[0];
    const int*   reply  = (const int*)d_in[1];
    const int*   lens   = (const int*)d_in[2];
    const float* label  = (const float*)d_in[3];
    const float* embed  = (const float*)d_in[4];
    const float* Wih_f  = (const float*)d_in[5];
    const float* Whh_f  = (const float*)d_in[6];
    const float* bih_f  = (const float*)d_in[7];
    const float* bhh_f  = (const float*)d_in[8];
    const float* Wih_b  = (const float*)d_in[9];
    const float* Whh_b  = (const float*)d_in[10];
    const float* bih_b  = (const float*)d_in[11];
    const float* bhh_b  = (const float*)d_in[12];
    const float* Wl     = (const float*)d_in[13];
    const float* bl     = (const float*)d_in[14];
    const float* Wo     = (const float*)d_in[15];
    const float* bo     = (const float*)d_in[16];
    float* out = (float*)d_out;

    embed_kernel<<<S, 320>>>(orig, reply, lens, embed);

    dim3 gi_grid((S + TT - 1) / TT, G3 / RR, 2);
    gi_kernel<<<gi_grid, 256>>>(Wih_f, bih_f, Wih_b, bih_b);

    gru_kernel<<<2 * NC, GRU_T>>>(Whh_f, bhh_f, Whh_b, bhh_b);

    dim3 op_grid((S + OTT - 1) / OTT, H / RR);   // 129 x 4
    outproj_kernel<<<op_grid, 256>>>(Wl, bl, out);

    attn_kernel<<<1, 1024>>>(out, Wo, bo, label, out + S * H);
}

// round 16
// speedup vs baseline: 2.8702x; 1.0262x over previous
#include <cuda_runtime.h>
#include <math_constants.h>

#define V  50000
#define E  300
#define H  256
#define R  2048
#define L0 128
#define LR 64
#define S  2049          // 1 + R
#define G3 768           // 3*H

#define NC     8         // CTAs per cluster (one cluster per direction)
#define DPC    32        // h-dims per CTA
#define GRU_T  384       // 12 warps x 8 rows = 96 rows per CTA
#define CTXB   32        // ctx partial blocks

// ---------------- scratch (device globals; no allocation allowed) -------------
__device__ float g_X[S * E];
__device__ float g_gi_f[S * G3];
__device__ float g_gi_b[S * G3];
__device__ float g_ys_f[S * H];
__device__ float g_ys_b[S * H];
__device__ float g_scores[S];
__device__ float g_wts[S];
__device__ float g_ctxp[CTXB * H];

// ---------------- small PTX helpers ------------------------------------------
__device__ __forceinline__ unsigned long long pk2(float lo, float hi) {
    unsigned long long r;
    asm("mov.b64 %0, {%1, %2};" : "=l"(r) : "f"(lo), "f"(hi));
    return r;
}
__device__ __forceinline__ float unpk_sum(unsigned long long v) {
    float a, b;
    asm("mov.b64 {%0, %1}, %2;" : "=f"(a), "=f"(b) : "l"(v));
    return a + b;
}
__device__ __forceinline__ unsigned long long ffma2(unsigned long long a,
                                                    unsigned long long b,
                                                    unsigned long long c) {
    unsigned long long d;
    asm("fma.rn.f32x2 %0, %1, %2, %3;" : "=l"(d) : "l"(a), "l"(b), "l"(c));
    return d;
}
__device__ __forceinline__ unsigned smem_u32(const void* p) {
    return (unsigned)__cvta_generic_to_shared(p);
}
__device__ __forceinline__ void mbar_init(unsigned addr, unsigned count) {
    asm volatile("mbarrier.init.shared.b64 [%0], %1;" :: "r"(addr), "r"(count) : "memory");
}
__device__ __forceinline__ void mbar_wait_cluster(unsigned addr, unsigned parity) {
    unsigned done;
    do {
        asm volatile(
            "{\n\t.reg .pred p;\n\t"
            "mbarrier.try_wait.parity.acquire.cluster.shared::cta.b64 p, [%1], %2, 0x989680;\n\t"
            "selp.b32 %0, 1, 0, p;\n\t}"
            : "=r"(done) : "r"(addr), "r"(parity) : "memory");
    } while (!done);
}
__device__ __forceinline__ unsigned cluster_rank() {
    unsigned r;
    asm("mov.u32 %0, %%cluster_ctarank;" : "=r"(r));
    return r;
}
__device__ __forceinline__ unsigned mapa_u32(unsigned addr, unsigned rank) {
    unsigned rem;
    asm("mapa.shared::cluster.u32 %0, %1, %2;" : "=r"(rem) : "r"(addr), "r"(rank));
    return rem;
}
__device__ __forceinline__ void st_cluster_f32(unsigned addr, float v) {
    asm volatile("st.shared::cluster.f32 [%0], %1;" :: "r"(addr), "f"(v) : "memory");
}
// plain (non-release) remote arrive — the R4-verified fast path
__device__ __forceinline__ void mbar_arrive_remote(unsigned addr) {
    asm volatile("mbarrier.arrive.shared::cluster.b64 _, [%0];" :: "r"(addr) : "memory");
}
__device__ __forceinline__ void cluster_sync() {
    asm volatile("barrier.cluster.arrive.aligned;" ::: "memory");
    asm volatile("barrier.cluster.wait.aligned;" ::: "memory");
}
__device__ __forceinline__ void bar_arrive_1() {
    asm volatile("bar.arrive 1, %0;" :: "r"(GRU_T) : "memory");
}
__device__ __forceinline__ void bar_sync_1() {
    asm volatile("bar.sync 1, %0;" :: "r"(GRU_T) : "memory");
}
// HW tanh (sm_75+): single special-function op, ~16 cyc
__device__ __forceinline__ float tanh_hw(float x) {
    float y;
    asm("tanh.approx.f32 %0, %1;" : "=f"(y) : "f"(x));
    return y;
}
// sigmoid via HW tanh: sigmoid(x) = 0.5*tanh(x/2) + 0.5
__device__ __forceinline__ float fsigmoid_hw(float x) {
    return fmaf(0.5f, tanh_hw(0.5f * x), 0.5f);
}

// ---------------- kernel 1: embedding sums -> X -------------------------------
__global__ void embed_kernel(const int* __restrict__ orig,
                             const int* __restrict__ reply,
                             const int* __restrict__ lens,
                             const float* __restrict__ embed) {
    int t = blockIdx.x;
    int e = threadIdx.x;
    if (e >= E) return;
    float acc = 0.f;
    if (t == 0) {
        #pragma unroll 4
        for (int l = 0; l < L0; ++l) {
            int tok = orig[l];
            acc += embed[(long long)tok * E + e];
        }
    } else {
        int r = t - 1;
        int len = lens[r];
        const int* rt = reply + r * LR;
        #pragma unroll 4
        for (int l = 0; l < len; ++l) {
            int tok = rt[l];
            acc += embed[(long long)tok * E + e];
        }
    }
    g_X[t * E + e] = acc;
}

// ---------------- kernel 2: gi GEMMs (both directions) ------------------------
#define TT 32
#define RR 64
#define KC 32
__global__ void gi_kernel(const float* __restrict__ Wf, const float* __restrict__ bf,
                          const float* __restrict__ Wb, const float* __restrict__ bb) {
    int dir = blockIdx.z;
    const float* W    = dir ? Wb : Wf;
    const float* bias = dir ? bb : bf;
    float* out        = dir ? g_gi_b : g_gi_f;
    int t0 = blockIdx.x * TT;
    int r0 = blockIdx.y * RR;

    __shared__ float Xs[TT][KC];
    __shared__ float Ws[RR][KC + 1];

    int tid = threadIdx.x;
    int r  = tid % RR;
    int tg = tid / RR;

    float acc[8];
    #pragma unroll
    for (int j = 0; j < 8; ++j) acc[j] = 0.f;

    for (int kk = 0; kk < E; kk += KC) {
        for (int i = tid; i < RR * KC; i += 256) {
            int rr = i / KC, k = i % KC;
            Ws[rr][k] = (kk + k < E) ? W[(r0 + rr) * E + kk + k] : 0.f;
        }
        for (int i = tid; i < TT * KC; i += 256) {
            int ttl = i / KC, k = i % KC;
            int t = t0 + ttl;
            float v = 0.f;
            if (t < S && kk + k < E) {
                int tsrc = dir ? (S - 1 - t) : t;
                v = g_X[tsrc * E + kk + k];
            }
            Xs[ttl][k] = v;
        }
        __syncthreads();
        #pragma unroll
        for (int k = 0; k < KC; ++k) {
            float wv = Ws[r][k];
            #pragma unroll
            for (int j = 0; j < 8; ++j)
                acc[j] += wv * Xs[tg * 8 + j][k];
        }
        __syncthreads();
    }
    float bv = bias[r0 + r];
    #pragma unroll
    for (int j = 0; j < 8; ++j) {
        int t = t0 + tg * 8 + j;
        if (t < S) out[t * G3 + r0 + r] = acc[j] + bv;
    }
}

// ---------------- kernel 3: GRU recurrence (R15 verified, unchanged) ----------
__global__ void __launch_bounds__(GRU_T, 1) __cluster_dims__(NC, 1, 1)
gru_kernel(const float* __restrict__ Whh_f, const float* __restrict__ bhh_f,
           const float* __restrict__ Whh_b, const float* __restrict__ bhh_b) {
    int dir = blockIdx.x >> 3;
    unsigned c = cluster_rank();
    const float* Whh = dir ? Whh_b : Whh_f;
    const float* bhh = dir ? bhh_b : bhh_f;
    const float* gi  = dir ? g_gi_b : g_gi_f;
    float* ys        = dir ? g_ys_b : g_ys_f;

    int tid  = threadIdx.x;
    int w    = tid >> 5;        // 0..11
    int lane = tid & 31;
    int base = (int)c * DPC;

    __shared__ __align__(16) float hbuf[2][H];   // double-buffered full h
    __shared__ __align__(16) float4 s_gh4[96];   // per-row octet partials
    __shared__ __align__(8) unsigned long long bars[2];

    unsigned hbuf_u32 = smem_u32(&hbuf[0][0]);
    unsigned bars_u32 = smem_u32(&bars[0]);

    if (tid == 0) { mbar_init(bars_u32, NC); mbar_init(bars_u32 + 8, NC); }
    if (tid < H) hbuf[0][tid] = 0.f;
    __syncthreads();
    cluster_sync();   // peers must not arrive on an uninitialized mbarrier

    // precomputed remote addresses (used by warp 0)
    unsigned remh[NC], remb[NC];
    #pragma unroll
    for (int r = 0; r < NC; ++r) {
        remh[r] = mapa_u32(hbuf_u32, (unsigned)r);
        remb[r] = mapa_u32(bars_u32, (unsigned)r);
    }

    // resident weights: 8 rows x 8 cols per lane, packed f32x2
    unsigned long long w2[8][4];
    #pragma unroll
    for (int k = 0; k < 8; ++k) {
        int lr = w * 8 + k;
        int row = (lr >> 5) * H + base + (lr & 31);
        const float* wr = Whh + (size_t)row * H + lane * 8;
        float4 a = *(const float4*)wr;
        float4 b = *(const float4*)(wr + 4);
        w2[k][0] = pk2(a.x, a.y); w2[k][1] = pk2(a.z, a.w);
        w2[k][2] = pk2(b.x, b.y); w2[k][3] = pk2(b.z, b.w);
    }
    // bias for row 8w+(lane&7); added only by the part-0 octet (lanes 0-7)
    float breg;
    {
        int lrb = w * 8 + (lane & 7);
        int rowb = (lrb >> 5) * H + base + (lrb & 31);
        breg = (lane < 8) ? bhh[rowb] : 0.f;
    }
    // flat STS index for this lane's partial (permutation of 0..31 per warp)
    unsigned gh_sts = smem_u32(&s_gh4[0]) +
        (unsigned)((w * 32 + (lane & 7) * 4 + (lane >> 3)) * 4);

    // warp0 per-lane gate state (lane = local dim)
    float gir = 0.f, giz = 0.f, gin = 0.f, hold = 0.f;
    if (w == 0) {
        int ii = base + lane;
        gir = gi[ii]; giz = gi[H + ii]; gin = gi[2 * H + ii];   // step 0
    }

    unsigned ph0 = 0, ph1 = 0;
    const unsigned FM = 0xffffffffu;

    for (int t = 0; t < S; ++t) {
        // prefetch gi for step t+1 (warp 0 only; hidden under dot+wait)
        float ngr = 0.f, ngz = 0.f, ngn = 0.f;
        if (w == 0 && t + 1 < S) {
            const float* gp = gi + (t + 1) * G3 + base + lane;
            ngr = __ldg(gp); ngz = __ldg(gp + H); ngn = __ldg(gp + 2 * H);
        }

        // wait for h_t in hbuf[t&1]; t=0 uses zeros
        if (t) {
            if (t & 1) { mbar_wait_cluster(bars_u32 + 8, ph1); ph1 ^= 1; }
            else       { mbar_wait_cluster(bars_u32,     ph0); ph0 ^= 1; }
        }

        // dot: 8 rows x 8 cols per lane; h loaded directly as f32x2 pairs
        const ulonglong2* hp =
            (const ulonglong2*)(&hbuf[t & 1][lane * 8]);
        ulonglong2 ha = hp[0];
        ulonglong2 hb = hp[1];
        unsigned long long h2[4];
        h2[0] = ha.x; h2[1] = ha.y; h2[2] = hb.x; h2[3] = hb.y;

        float p[8];
        #pragma unroll
        for (int k = 0; k < 8; ++k) {
            unsigned long long acc = ffma2(w2[k][0], h2[0], 0ULL);
            acc = ffma2(w2[k][1], h2[1], acc);
            acc = ffma2(w2[k][2], h2[2], acc);
            acc = ffma2(w2[k][3], h2[3], acc);
            p[k] = unpk_sum(acc);
        }

        // fold reduce TRUNCATED at depth 3: u = octet partial of row 8w+(lane&7)
        bool b0 = (lane & 1), b1 = (lane & 2), b2 = (lane & 4);
        float q0, q1, q2, q3, r0v, r1v, u;
        { float v = b0 ? p[0] : p[1]; float sx = __shfl_xor_sync(FM, v, 1);
          q0 = (b0 ? p[1] : p[0]) + sx; }
        { float v = b0 ? p[2] : p[3]; float sx = __shfl_xor_sync(FM, v, 1);
          q1 = (b0 ? p[3] : p[2]) + sx; }
        { float v = b0 ? p[4] : p[5]; float sx = __shfl_xor_sync(FM, v, 1);
          q2 = (b0 ? p[5] : p[4]) + sx; }
        { float v = b0 ? p[6] : p[7]; float sx = __shfl_xor_sync(FM, v, 1);
          q3 = (b0 ? p[7] : p[6]) + sx; }
        { float v = b1 ? q0 : q1; float sx = __shfl_xor_sync(FM, v, 2);
          r0v = (b1 ? q1 : q0) + sx; }
        { float v = b1 ? q2 : q3; float sx = __shfl_xor_sync(FM, v, 2);
          r1v = (b1 ? q3 : q2) + sx; }
        { float v = b2 ? r0v : r1v; float sx = __shfl_xor_sync(FM, v, 4);
          u = (b2 ? r1v : r0v) + sx; }
        // all 32 lanes store their octet partial (+bias in part 0)
        asm volatile("st.shared.f32 [%0], %1;" :: "r"(gh_sts), "f"(u + breg) : "memory");

        if (w != 0) {
            bar_arrive_1();        // non-blocking; next stop: mbar wait t+1
        } else {
            bar_sync_1();          // wait for all 12 warps' STS (BAR drains STS)
            // gates: lane = local dim; sum 4 octet partials per row (LDS.128)
            float4 vr = s_gh4[lane];
            float4 vz = s_gh4[32 + lane];
            float4 vn = s_gh4[64 + lane];
            float ghr = (vr.x + vr.y) + (vr.z + vr.w);
            float ghz = (vz.x + vz.y) + (vz.z + vz.w);
            float ghn = (vn.x + vn.y) + (vn.z + vn.w);
            float rr = fsigmoid_hw(gir + ghr);
            float zz = fsigmoid_hw(giz + ghz);
            float nn = tanh_hw(fmaf(rr, ghn, gin));
            float hn = fmaf(zz, hold - nn, nn);
            hold = hn;

            // publish h_{t+1} to all 8 CTAs (register-direct DSMEM stores)
            if (t + 1 < S) {
                unsigned off = (unsigned)(((t + 1) & 1) * (H * 4) + (base + lane) * 4);
                #pragma unroll
                for (int r = 0; r < NC; ++r)
                    st_cluster_f32(remh[r] + off, hn);
                __syncwarp();
                if (lane < NC)
                    mbar_arrive_remote(remb[lane] + ((t + 1) & 1) * 8);
            }

            int trow = dir ? (S - 1 - t) : t;
            ys[trow * H + base + lane] = hn;
            gir = ngr; giz = ngz; gin = ngn;
        }
    }
    cluster_sync();
}

// ---------------- kernel 4: output projection --------------------------------
#define OTT 16
__global__ void outproj_kernel(const float* __restrict__ Wl,
                               const float* __restrict__ bl,
                               float* __restrict__ outbuf) {
    int t0 = blockIdx.x * OTT;
    int j0 = blockIdx.y * RR;
    __shared__ float As[OTT][KC];
    __shared__ float Ws[RR][KC + 1];
    int tid = threadIdx.x;
    int r  = tid % RR;
    int tg = tid / RR;
    float acc[4];
    #pragma unroll
    for (int j = 0; j < 4; ++j) acc[j] = 0.f;

    for (int kk = 0; kk < 2 * H; kk += KC) {
        const float* ysrc = (kk < H) ? g_ys_f : g_ys_b;
        int kbase = (kk < H) ? kk : (kk - H);
        for (int i = tid; i < RR * KC; i += 256) {
            int rr = i / KC, k = i % KC;
            Ws[rr][k] = Wl[(j0 + rr) * (2 * H) + kk + k];
        }
        for (int i = tid; i < OTT * KC; i += 256) {
            int ttl = i / KC, k = i % KC;
            int t = t0 + ttl;
            As[ttl][k] = (t < S) ? ysrc[t * H + kbase + k] : 0.f;
        }
        __syncthreads();
        #pragma unroll
        for (int k = 0; k < KC; ++k) {
            float wv = Ws[r][k];
            #pragma unroll
            for (int j = 0; j < 4; ++j)
                acc[j] += wv * As[tg * 4 + j][k];
        }
        __syncthreads();
    }
    float bv = bl[j0 + r];
    #pragma unroll
    for (int j = 0; j < 4; ++j) {
        int t = t0 + tg * 4 + j;
        if (t < S) outbuf[t * H + j0 + r] = acc[j] + bv;
    }
}

// ---------------- kernel 5a: attention scores (grid-parallel) -----------------
// Block handles 32 rows (8 warps x 4 rows). scores[t] = out[t] . (h_f + h_b)
__global__ void scores_kernel(const float* __restrict__ outbuf) {
    __shared__ float s_hsum[H];
    int tid = threadIdx.x;
    int wp  = tid >> 5;
    int ln  = tid & 31;

    if (tid < H) s_hsum[tid] = g_ys_f[(S - 1) * H + tid] + g_ys_b[tid];
    __syncthreads();

    int t0 = blockIdx.x * 32;
    #pragma unroll
    for (int i = 0; i < 4; ++i) {
        int t = t0 + wp + 8 * i;
        if (t >= S) continue;
        const float* o = outbuf + t * H;
        float s = 0.f;
        #pragma unroll
        for (int k = ln; k < H; k += 32) s += o[k] * s_hsum[k];
        s += __shfl_down_sync(0xffffffffu, s, 16);
        s += __shfl_down_sync(0xffffffffu, s, 8);
        s += __shfl_down_sync(0xffffffffu, s, 4);
        s += __shfl_down_sync(0xffffffffu, s, 2);
        s += __shfl_down_sync(0xffffffffu, s, 1);
        if (ln == 0) g_scores[t] = s;
    }
}

// ---------------- kernel 5b: softmax over scores (single small block) ---------
__global__ void softmax_kernel() {
    __shared__ float s_red[32];
    int tid = threadIdx.x;    // 1024
    int wp  = tid >> 5;
    int ln  = tid & 31;

    float m = -CUDART_INF_F;
    for (int t = tid; t < S; t += 1024) m = fmaxf(m, g_scores[t]);
    for (int off = 16; off >= 1; off >>= 1)
        m = fmaxf(m, __shfl_down_sync(0xffffffffu, m, off));
    if (ln == 0) s_red[wp] = m;
    __syncthreads();
    if (tid < 32) {
        float mm = s_red[tid];
        for (int off = 16; off >= 1; off >>= 1)
            mm = fmaxf(mm, __shfl_down_sync(0xffffffffu, mm, off));
        if (tid == 0) s_red[0] = mm;
    }
    __syncthreads();
    float M = s_red[0];
    __syncthreads();

    float lsum = 0.f;
    for (int t = tid; t < S; t += 1024) lsum += expf(g_scores[t] - M);
    for (int off = 16; off >= 1; off >>= 1)
        lsum += __shfl_down_sync(0xffffffffu, lsum, off);
    if (ln == 0) s_red[wp] = lsum;
    __syncthreads();
    if (tid < 32) {
        float ss = s_red[tid];
        for (int off = 16; off >= 1; off >>= 1)
            ss += __shfl_down_sync(0xffffffffu, ss, off);
        if (tid == 0) s_red[0] = ss;
    }
    __syncthreads();
    float inv = 1.f / s_red[0];

    for (int t = tid; t < S; t += 1024)
        g_wts[t] = expf(g_scores[t] - M) * inv;
}

// ---------------- kernel 5c: ctx partials (grid-parallel) ---------------------
// Block b accumulates w[t]*out[t,j] over rows t = b, b+32, b+64, ...
__global__ void ctxpart_kernel(const float* __restrict__ outbuf) {
    int j = threadIdx.x;     // 0..255
    int b = blockIdx.x;      // 0..31
    float acc = 0.f;
    for (int t = b; t < S; t += CTXB)
        acc += g_wts[t] * outbuf[t * H + j];
    g_ctxp[b * H + j] = acc;
}

// ---------------- kernel 5d: final head (tiny) --------------------------------
__global__ void head_kernel(const float* __restrict__ Wo,
                            const float* __restrict__ bo,
                            const float* __restrict__ label,
                            float* __restrict__ tail) {
    __shared__ float s_v[H];
    int tid = threadIdx.x;   // 256
    float cj = 0.f;
    #pragma unroll
    for (int b = 0; b < CTXB; ++b) cj += g_ctxp[b * H + tid];
    s_v[tid] = cj * Wo[tid];
    __syncthreads();
    if (tid < 32) {
        float a = 0.f;
        #pragma unroll
        for (int q = 0; q < 8; ++q) a += s_v[tid + q * 32];
        for (int off = 16; off >= 1; off >>= 1)
            a += __shfl_down_sync(0xffffffffu, a, off);
        if (tid == 0) {
            float res = 1.f / (1.f + expf(-(a + bo[0])));
            float d = label[0] - res;
            tail[0] = d * d;
            tail[1] = res;
        }
    }
}

// ---------------- launch ------------------------------------------------------
extern "C" void kernel_launch(void* const* d_in, const int* in_sizes, int n_in,
                              void* d_out, int out_size) {
    const int*   orig   = (const int*)d_in[0];
    const int*   reply  = (const int*)d_in[1];
    const int*   lens   = (const int*)d_in[2];
    const float* label  = (const float*)d_in[3];
    const float* embed  = (const float*)d_in[4];
    const float* Wih_f  = (const float*)d_in[5];
    const float* Whh_f  = (const float*)d_in[6];
    const float* bih_f  = (const float*)d_in[7];
    const float* bhh_f  = (const float*)d_in[8];
    const float* Wih_b  = (const float*)d_in[9];
    const float* Whh_b  = (const float*)d_in[10];
    const float* bih_b  = (const float*)d_in[11];
    const float* bhh_b  = (const float*)d_in[12];
    const float* Wl     = (const float*)d_in[13];
    const float* bl     = (const float*)d_in[14];
    const float* Wo     = (const float*)d_in[15];
    const float* bo     = (const float*)d_in[16];
    float* out = (float*)d_out;

    embed_kernel<<<S, 320>>>(orig, reply, lens, embed);

    dim3 gi_grid((S + TT - 1) / TT, G3 / RR, 2);
    gi_kernel<<<gi_grid, 256>>>(Wih_f, bih_f, Wih_b, bih_b);

    gru_kernel<<<2 * NC, GRU_T>>>(Whh_f, bhh_f, Whh_b, bhh_b);

    dim3 op_grid((S + OTT - 1) / OTT, H / RR);   // 129 x 4
    outproj_kernel<<<op_grid, 256>>>(Wl, bl, out);

    scores_kernel<<<(S + 31) / 32, 256>>>(out);   // 65 blocks
    softmax_kernel<<<1, 1024>>>();
    ctxpart_kernel<<<CTXB, 256>>>(out);
    head_kernel<<<1, 256>>>(Wo, bo, label, out + S * H);
}

// round 17
// speedup vs baseline: 2.9451x; 1.0261x over previous
#include <cuda_runtime.h>
#include <math_constants.h>

#define V  50000
#define E  300
#define H  256
#define R  2048
#define L0 128
#define LR 64
#define S  2049          // 1 + R
#define G3 768           // 3*H

#define NC     8         // CTAs per cluster (one cluster per direction)
#define DPC    32        // h-dims per CTA
#define GRU_T  384       // 12 warps x 8 rows = 96 rows per CTA
#define CTXB   32        // ctx partial blocks

// ---------------- scratch (device globals; no allocation allowed) -------------
__device__ float g_X[S * E];
__device__ float g_gi_f[S * G3];
__device__ float g_gi_b[S * G3];
__device__ float g_ys_f[S * H];
__device__ float g_ys_b[S * H];
__device__ float g_scores[S];
__device__ float g_wts[S];
__device__ float g_ctxp[CTXB * H];

// ---------------- small PTX helpers ------------------------------------------
__device__ __forceinline__ unsigned long long pk2(float lo, float hi) {
    unsigned long long r;
    asm("mov.b64 %0, {%1, %2};" : "=l"(r) : "f"(lo), "f"(hi));
    return r;
}
__device__ __forceinline__ float unpk_sum(unsigned long long v) {
    float a, b;
    asm("mov.b64 {%0, %1}, %2;" : "=f"(a), "=f"(b) : "l"(v));
    return a + b;
}
__device__ __forceinline__ unsigned long long ffma2(unsigned long long a,
                                                    unsigned long long b,
                                                    unsigned long long c) {
    unsigned long long d;
    asm("fma.rn.f32x2 %0, %1, %2, %3;" : "=l"(d) : "l"(a), "l"(b), "l"(c));
    return d;
}
__device__ __forceinline__ unsigned smem_u32(const void* p) {
    return (unsigned)__cvta_generic_to_shared(p);
}
__device__ __forceinline__ void mbar_init(unsigned addr, unsigned count) {
    asm volatile("mbarrier.init.shared.b64 [%0], %1;" :: "r"(addr), "r"(count) : "memory");
}
__device__ __forceinline__ void mbar_wait_cluster(unsigned addr, unsigned parity) {
    unsigned done;
    do {
        asm volatile(
            "{\n\t.reg .pred p;\n\t"
            "mbarrier.try_wait.parity.acquire.cluster.shared::cta.b64 p, [%1], %2, 0x989680;\n\t"
            "selp.b32 %0, 1, 0, p;\n\t}"
            : "=r"(done) : "r"(addr), "r"(parity) : "memory");
    } while (!done);
}
__device__ __forceinline__ unsigned cluster_rank() {
    unsigned r;
    asm("mov.u32 %0, %%cluster_ctarank;" : "=r"(r));
    return r;
}
__device__ __forceinline__ unsigned mapa_u32(unsigned addr, unsigned rank) {
    unsigned rem;
    asm("mapa.shared::cluster.u32 %0, %1, %2;" : "=r"(rem) : "r"(addr), "r"(rank));
    return rem;
}
__device__ __forceinline__ void st_cluster_f32(unsigned addr, float v) {
    asm volatile("st.shared::cluster.f32 [%0], %1;" :: "r"(addr), "f"(v) : "memory");
}
// plain (non-release) remote arrive — the R4-verified fast path
__device__ __forceinline__ void mbar_arrive_remote(unsigned addr) {
    asm volatile("mbarrier.arrive.shared::cluster.b64 _, [%0];" :: "r"(addr) : "memory");
}
__device__ __forceinline__ void cluster_sync() {
    asm volatile("barrier.cluster.arrive.aligned;" ::: "memory");
    asm volatile("barrier.cluster.wait.aligned;" ::: "memory");
}
__device__ __forceinline__ void bar_arrive_1() {
    asm volatile("bar.arrive 1, %0;" :: "r"(GRU_T) : "memory");
}
__device__ __forceinline__ void bar_sync_1() {
    asm volatile("bar.sync 1, %0;" :: "r"(GRU_T) : "memory");
}
// HW tanh (sm_75+): single special-function op, ~16 cyc
__device__ __forceinline__ float tanh_hw(float x) {
    float y;
    asm("tanh.approx.f32 %0, %1;" : "=f"(y) : "f"(x));
    return y;
}
// sigmoid via HW tanh: sigmoid(x) = 0.5*tanh(x/2) + 0.5
__device__ __forceinline__ float fsigmoid_hw(float x) {
    return fmaf(0.5f, tanh_hw(0.5f * x), 0.5f);
}

// ---------------- kernel 1: embedding sums -> X -------------------------------
__global__ void embed_kernel(const int* __restrict__ orig,
                             const int* __restrict__ reply,
                             const int* __restrict__ lens,
                             const float* __restrict__ embed) {
    int t = blockIdx.x;
    int e = threadIdx.x;
    if (e >= E) return;
    float acc = 0.f;
    if (t == 0) {
        #pragma unroll 4
        for (int l = 0; l < L0; ++l) {
            int tok = orig[l];
            acc += embed[(long long)tok * E + e];
        }
    } else {
        int r = t - 1;
        int len = lens[r];
        const int* rt = reply + r * LR;
        #pragma unroll 4
        for (int l = 0; l < len; ++l) {
            int tok = rt[l];
            acc += embed[(long long)tok * E + e];
        }
    }
    g_X[t * E + e] = acc;
}

// ---------------- kernel 2: gi GEMM, 64x64 tile, 4x4 register micro-tile ------
// out[t, r] = bias[r] + sum_k W[r,k] * X[tsrc,k]; K = E = 300 (19 chunks of 16,
// zero-padded; E % 4 == 0 so all float4 loads with kbase < E are in-bounds).
__global__ void __launch_bounds__(256, 2)
gi_kernel(const float* __restrict__ Wf, const float* __restrict__ bf,
          const float* __restrict__ Wb, const float* __restrict__ bb) {
    int dir = blockIdx.z;
    const float* W    = dir ? Wb : Wf;
    const float* bias = dir ? bb : bf;
    float* out        = dir ? g_gi_b : g_gi_f;
    int t0 = blockIdx.x * 64;
    int r0 = blockIdx.y * 64;

    __shared__ float Xs[16][68];   // [k][t], stride 68 -> 16B-aligned rows
    __shared__ float Ws[16][68];   // [k][r]

    int tid = threadIdx.x;
    int ldr = tid >> 2;            // 0..63: tile row to load
    int ldk = (tid & 3) * 4;       // k offset within chunk
    int tx  = tid & 15;            // t micro-tile index
    int ty  = tid >> 4;            // r micro-tile index

    float acc[4][4];               // [r][t]
    #pragma unroll
    for (int i = 0; i < 4; ++i)
        #pragma unroll
        for (int j = 0; j < 4; ++j) acc[i][j] = 0.f;

    int tld = t0 + ldr;
    bool tok = (tld < S);
    int tsrc = dir ? (S - 1 - tld) : tld;
    const float* xrow = g_X + (size_t)(tok ? tsrc : 0) * E;
    const float* wrow = W + (size_t)(r0 + ldr) * E;

    for (int kk = 0; kk < 304; kk += 16) {
        int kbase = kk + ldk;
        float4 wv = make_float4(0.f, 0.f, 0.f, 0.f);
        float4 xv = make_float4(0.f, 0.f, 0.f, 0.f);
        if (kbase < E) {
            wv = *(const float4*)(wrow + kbase);
            if (tok) xv = *(const float4*)(xrow + kbase);
        }
        Ws[ldk + 0][ldr] = wv.x; Ws[ldk + 1][ldr] = wv.y;
        Ws[ldk + 2][ldr] = wv.z; Ws[ldk + 3][ldr] = wv.w;
        Xs[ldk + 0][ldr] = xv.x; Xs[ldk + 1][ldr] = xv.y;
        Xs[ldk + 2][ldr] = xv.z; Xs[ldk + 3][ldr] = xv.w;
        __syncthreads();

        #pragma unroll
        for (int k = 0; k < 16; ++k) {
            float4 xa = *(const float4*)&Xs[k][tx * 4];
            float4 wa = *(const float4*)&Ws[k][ty * 4];
            acc[0][0] += wa.x * xa.x; acc[0][1] += wa.x * xa.y;
            acc[0][2] += wa.x * xa.z; acc[0][3] += wa.x * xa.w;
            acc[1][0] += wa.y * xa.x; acc[1][1] += wa.y * xa.y;
            acc[1][2] += wa.y * xa.z; acc[1][3] += wa.y * xa.w;
            acc[2][0] += wa.z * xa.x; acc[2][1] += wa.z * xa.y;
            acc[2][2] += wa.z * xa.z; acc[2][3] += wa.z * xa.w;
            acc[3][0] += wa.w * xa.x; acc[3][1] += wa.w * xa.y;
            acc[3][2] += wa.w * xa.z; acc[3][3] += wa.w * xa.w;
        }
        __syncthreads();
    }

    float4 bv = *(const float4*)(bias + r0 + ty * 4);
    #pragma unroll
    for (int j = 0; j < 4; ++j) {
        int t = t0 + tx * 4 + j;
        if (t < S) {
            float4 o;
            o.x = acc[0][j] + bv.x; o.y = acc[1][j] + bv.y;
            o.z = acc[2][j] + bv.z; o.w = acc[3][j] + bv.w;
            *(float4*)(out + (size_t)t * G3 + r0 + ty * 4) = o;
        }
    }
}

// ---------------- kernel 3: GRU recurrence (R15 verified, unchanged) ----------
__global__ void __launch_bounds__(GRU_T, 1) __cluster_dims__(NC, 1, 1)
gru_kernel(const float* __restrict__ Whh_f, const float* __restrict__ bhh_f,
           const float* __restrict__ Whh_b, const float* __restrict__ bhh_b) {
    int dir = blockIdx.x >> 3;
    unsigned c = cluster_rank();
    const float* Whh = dir ? Whh_b : Whh_f;
    const float* bhh = dir ? bhh_b : bhh_f;
    const float* gi  = dir ? g_gi_b : g_gi_f;
    float* ys        = dir ? g_ys_b : g_ys_f;

    int tid  = threadIdx.x;
    int w    = tid >> 5;        // 0..11
    int lane = tid & 31;
    int base = (int)c * DPC;

    __shared__ __align__(16) float hbuf[2][H];   // double-buffered full h
    __shared__ __align__(16) float4 s_gh4[96];   // per-row octet partials
    __shared__ __align__(8) unsigned long long bars[2];

    unsigned hbuf_u32 = smem_u32(&hbuf[0][0]);
    unsigned bars_u32 = smem_u32(&bars[0]);

    if (tid == 0) { mbar_init(bars_u32, NC); mbar_init(bars_u32 + 8, NC); }
    if (tid < H) hbuf[0][tid] = 0.f;
    __syncthreads();
    cluster_sync();   // peers must not arrive on an uninitialized mbarrier

    // precomputed remote addresses (used by warp 0)
    unsigned remh[NC], remb[NC];
    #pragma unroll
    for (int r = 0; r < NC; ++r) {
        remh[r] = mapa_u32(hbuf_u32, (unsigned)r);
        remb[r] = mapa_u32(bars_u32, (unsigned)r);
    }

    // resident weights: 8 rows x 8 cols per lane, packed f32x2
    unsigned long long w2[8][4];
    #pragma unroll
    for (int k = 0; k < 8; ++k) {
        int lr = w * 8 + k;
        int row = (lr >> 5) * H + base + (lr & 31);
        const float* wr = Whh + (size_t)row * H + lane * 8;
        float4 a = *(const float4*)wr;
        float4 b = *(const float4*)(wr + 4);
        w2[k][0] = pk2(a.x, a.y); w2[k][1] = pk2(a.z, a.w);
        w2[k][2] = pk2(b.x, b.y); w2[k][3] = pk2(b.z, b.w);
    }
    // bias for row 8w+(lane&7); added only by the part-0 octet (lanes 0-7)
    float breg;
    {
        int lrb = w * 8 + (lane & 7);
        int rowb = (lrb >> 5) * H + base + (lrb & 31);
        breg = (lane < 8) ? bhh[rowb] : 0.f;
    }
    // flat STS index for this lane's partial (permutation of 0..31 per warp)
    unsigned gh_sts = smem_u32(&s_gh4[0]) +
        (unsigned)((w * 32 + (lane & 7) * 4 + (lane >> 3)) * 4);

    // warp0 per-lane gate state (lane = local dim)
    float gir = 0.f, giz = 0.f, gin = 0.f, hold = 0.f;
    if (w == 0) {
        int ii = base + lane;
        gir = gi[ii]; giz = gi[H + ii]; gin = gi[2 * H + ii];   // step 0
    }

    unsigned ph0 = 0, ph1 = 0;
    const unsigned FM = 0xffffffffu;

    for (int t = 0; t < S; ++t) {
        // prefetch gi for step t+1 (warp 0 only; hidden under dot+wait)
        float ngr = 0.f, ngz = 0.f, ngn = 0.f;
        if (w == 0 && t + 1 < S) {
            const float* gp = gi + (t + 1) * G3 + base + lane;
            ngr = __ldg(gp); ngz = __ldg(gp + H); ngn = __ldg(gp + 2 * H);
        }

        // wait for h_t in hbuf[t&1]; t=0 uses zeros
        if (t) {
            if (t & 1) { mbar_wait_cluster(bars_u32 + 8, ph1); ph1 ^= 1; }
            else       { mbar_wait_cluster(bars_u32,     ph0); ph0 ^= 1; }
        }

        // dot: 8 rows x 8 cols per lane; h loaded directly as f32x2 pairs
        const ulonglong2* hp =
            (const ulonglong2*)(&hbuf[t & 1][lane * 8]);
        ulonglong2 ha = hp[0];
        ulonglong2 hb = hp[1];
        unsigned long long h2[4];
        h2[0] = ha.x; h2[1] = ha.y; h2[2] = hb.x; h2[3] = hb.y;

        float p[8];
        #pragma unroll
        for (int k = 0; k < 8; ++k) {
            unsigned long long acc = ffma2(w2[k][0], h2[0], 0ULL);
            acc = ffma2(w2[k][1], h2[1], acc);
            acc = ffma2(w2[k][2], h2[2], acc);
            acc = ffma2(w2[k][3], h2[3], acc);
            p[k] = unpk_sum(acc);
        }

        // fold reduce TRUNCATED at depth 3: u = octet partial of row 8w+(lane&7)
        bool b0 = (lane & 1), b1 = (lane & 2), b2 = (lane & 4);
        float q0, q1, q2, q3, r0v, r1v, u;
        { float v = b0 ? p[0] : p[1]; float sx = __shfl_xor_sync(FM, v, 1);
          q0 = (b0 ? p[1] : p[0]) + sx; }
        { float v = b0 ? p[2] : p[3]; float sx = __shfl_xor_sync(FM, v, 1);
          q1 = (b0 ? p[3] : p[2]) + sx; }
        { float v = b0 ? p[4] : p[5]; float sx = __shfl_xor_sync(FM, v, 1);
          q2 = (b0 ? p[5] : p[4]) + sx; }
        { float v = b0 ? p[6] : p[7]; float sx = __shfl_xor_sync(FM, v, 1);
          q3 = (b0 ? p[7] : p[6]) + sx; }
        { float v = b1 ? q0 : q1; float sx = __shfl_xor_sync(FM, v, 2);
          r0v = (b1 ? q1 : q0) + sx; }
        { float v = b1 ? q2 : q3; float sx = __shfl_xor_sync(FM, v, 2);
          r1v = (b1 ? q3 : q2) + sx; }
        { float v = b2 ? r0v : r1v; float sx = __shfl_xor_sync(FM, v, 4);
          u = (b2 ? r1v : r0v) + sx; }
        // all 32 lanes store their octet partial (+bias in part 0)
        asm volatile("st.shared.f32 [%0], %1;" :: "r"(gh_sts), "f"(u + breg) : "memory");

        if (w != 0) {
            bar_arrive_1();        // non-blocking; next stop: mbar wait t+1
        } else {
            bar_sync_1();          // wait for all 12 warps' STS (BAR drains STS)
            // gates: lane = local dim; sum 4 octet partials per row (LDS.128)
            float4 vr = s_gh4[lane];
            float4 vz = s_gh4[32 + lane];
            float4 vn = s_gh4[64 + lane];
            float ghr = (vr.x + vr.y) + (vr.z + vr.w);
            float ghz = (vz.x + vz.y) + (vz.z + vz.w);
            float ghn = (vn.x + vn.y) + (vn.z + vn.w);
            float rr = fsigmoid_hw(gir + ghr);
            float zz = fsigmoid_hw(giz + ghz);
            float nn = tanh_hw(fmaf(rr, ghn, gin));
            float hn = fmaf(zz, hold - nn, nn);
            hold = hn;

            // publish h_{t+1} to all 8 CTAs (register-direct DSMEM stores)
            if (t + 1 < S) {
                unsigned off = (unsigned)(((t + 1) & 1) * (H * 4) + (base + lane) * 4);
                #pragma unroll
                for (int r = 0; r < NC; ++r)
                    st_cluster_f32(remh[r] + off, hn);
                __syncwarp();
                if (lane < NC)
                    mbar_arrive_remote(remb[lane] + ((t + 1) & 1) * 8);
            }

            int trow = dir ? (S - 1 - t) : t;
            ys[trow * H + base + lane] = hn;
            gir = ngr; giz = ngz; gin = ngn;
        }
    }
    cluster_sync();
}

// ---------------- kernel 4: output projection, 64x64 tile, 4x4 micro-tile -----
// out[t, j] = bl[j] + sum_{k<512} ysrc[t, k] * Wl[j, k]; k<256 -> ys_f, else ys_b
__global__ void __launch_bounds__(256, 2)
outproj_kernel(const float* __restrict__ Wl, const float* __restrict__ bl,
               float* __restrict__ outbuf) {
    int t0 = blockIdx.x * 64;
    int j0 = blockIdx.y * 64;

    __shared__ float Xs[16][68];   // [k][t]
    __shared__ float Ws[16][68];   // [k][j]

    int tid = threadIdx.x;
    int ldr = tid >> 2;
    int ldk = (tid & 3) * 4;
    int tx  = tid & 15;
    int ty  = tid >> 4;

    float acc[4][4];
    #pragma unroll
    for (int i = 0; i < 4; ++i)
        #pragma unroll
        for (int j = 0; j < 4; ++j) acc[i][j] = 0.f;

    int tld = t0 + ldr;
    bool tokv = (tld < S);
    const float* wrow = Wl + (size_t)(j0 + ldr) * (2 * H);

    for (int kk = 0; kk < 2 * H; kk += 16) {
        int kbase = kk + ldk;
        float4 wv = *(const float4*)(wrow + kbase);
        float4 xv = make_float4(0.f, 0.f, 0.f, 0.f);
        if (tokv) {
            const float* ysrc = (kbase < H) ? (g_ys_f + (size_t)tld * H + kbase)
                                            : (g_ys_b + (size_t)tld * H + (kbase - H));
            xv = *(const float4*)ysrc;
        }
        Ws[ldk + 0][ldr] = wv.x; Ws[ldk + 1][ldr] = wv.y;
        Ws[ldk + 2][ldr] = wv.z; Ws[ldk + 3][ldr] = wv.w;
        Xs[ldk + 0][ldr] = xv.x; Xs[ldk + 1][ldr] = xv.y;
        Xs[ldk + 2][ldr] = xv.z; Xs[ldk + 3][ldr] = xv.w;
        __syncthreads();

        #pragma unroll
        for (int k = 0; k < 16; ++k) {
            float4 xa = *(const float4*)&Xs[k][tx * 4];
            float4 wa = *(const float4*)&Ws[k][ty * 4];
            acc[0][0] += wa.x * xa.x; acc[0][1] += wa.x * xa.y;
            acc[0][2] += wa.x * xa.z; acc[0][3] += wa.x * xa.w;
            acc[1][0] += wa.y * xa.x; acc[1][1] += wa.y * xa.y;
            acc[1][2] += wa.y * xa.z; acc[1][3] += wa.y * xa.w;
            acc[2][0] += wa.z * xa.x; acc[2][1] += wa.z * xa.y;
            acc[2][2] += wa.z * xa.z; acc[2][3] += wa.z * xa.w;
            acc[3][0] += wa.w * xa.x; acc[3][1] += wa.w * xa.y;
            acc[3][2] += wa.w * xa.z; acc[3][3] += wa.w * xa.w;
        }
        __syncthreads();
    }

    float4 bv = *(const float4*)(bl + j0 + ty * 4);
    #pragma unroll
    for (int j = 0; j < 4; ++j) {
        int t = t0 + tx * 4 + j;
        if (t < S) {
            float4 o;
            o.x = acc[0][j] + bv.x; o.y = acc[1][j] + bv.y;
            o.z = acc[2][j] + bv.z; o.w = acc[3][j] + bv.w;
            *(float4*)(outbuf + (size_t)t * H + j0 + ty * 4) = o;
        }
    }
}

// ---------------- kernel 5a: attention scores (grid-parallel) -----------------
__global__ void scores_kernel(const float* __restrict__ outbuf) {
    __shared__ float s_hsum[H];
    int tid = threadIdx.x;
    int wp  = tid >> 5;
    int ln  = tid & 31;

    if (tid < H) s_hsum[tid] = g_ys_f[(S - 1) * H + tid] + g_ys_b[tid];
    __syncthreads();

    int t0 = blockIdx.x * 32;
    #pragma unroll
    for (int i = 0; i < 4; ++i) {
        int t = t0 + wp + 8 * i;
        if (t >= S) continue;
        const float* o = outbuf + t * H;
        float s = 0.f;
        #pragma unroll
        for (int k = ln; k < H; k += 32) s += o[k] * s_hsum[k];
        s += __shfl_down_sync(0xffffffffu, s, 16);
        s += __shfl_down_sync(0xffffffffu, s, 8);
        s += __shfl_down_sync(0xffffffffu, s, 4);
        s += __shfl_down_sync(0xffffffffu, s, 2);
        s += __shfl_down_sync(0xffffffffu, s, 1);
        if (ln == 0) g_scores[t] = s;
    }
}

// ---------------- kernel 5b: softmax over scores (single small block) ---------
__global__ void softmax_kernel() {
    __shared__ float s_red[32];
    int tid = threadIdx.x;    // 1024
    int wp  = tid >> 5;
    int ln  = tid & 31;

    float m = -CUDART_INF_F;
    for (int t = tid; t < S; t += 1024) m = fmaxf(m, g_scores[t]);
    for (int off = 16; off >= 1; off >>= 1)
        m = fmaxf(m, __shfl_down_sync(0xffffffffu, m, off));
    if (ln == 0) s_red[wp] = m;
    __syncthreads();
    if (tid < 32) {
        float mm = s_red[tid];
        for (int off = 16; off >= 1; off >>= 1)
            mm = fmaxf(mm, __shfl_down_sync(0xffffffffu, mm, off));
        if (tid == 0) s_red[0] = mm;
    }
    __syncthreads();
    float M = s_red[0];
    __syncthreads();

    float lsum = 0.f;
    for (int t = tid; t < S; t += 1024) lsum += expf(g_scores[t] - M);
    for (int off = 16; off >= 1; off >>= 1)
        lsum += __shfl_down_sync(0xffffffffu, lsum, off);
    if (ln == 0) s_red[wp] = lsum;
    __syncthreads();
    if (tid < 32) {
        float ss = s_red[tid];
        for (int off = 16; off >= 1; off >>= 1)
            ss += __shfl_down_sync(0xffffffffu, ss, off);
        if (tid == 0) s_red[0] = ss;
    }
    __syncthreads();
    float inv = 1.f / s_red[0];

    for (int t = tid; t < S; t += 1024)
        g_wts[t] = expf(g_scores[t] - M) * inv;
}

// ---------------- kernel 5c: ctx partials (grid-parallel) ---------------------
__global__ void ctxpart_kernel(const float* __restrict__ outbuf) {
    int j = threadIdx.x;     // 0..255
    int b = blockIdx.x;      // 0..31
    float acc = 0.f;
    for (int t = b; t < S; t += CTXB)
        acc += g_wts[t] * outbuf[t * H + j];
    g_ctxp[b * H + j] = acc;
}

// ---------------- kernel 5d: final head (tiny) --------------------------------
__global__ void head_kernel(const float* __restrict__ Wo,
                            const float* __restrict__ bo,
                            const float* __restrict__ label,
                            float* __restrict__ tail) {
    __shared__ float s_v[H];
    int tid = threadIdx.x;   // 256
    float cj = 0.f;
    #pragma unroll
    for (int b = 0; b < CTXB; ++b) cj += g_ctxp[b * H + tid];
    s_v[tid] = cj * Wo[tid];
    __syncthreads();
    if (tid < 32) {
        float a = 0.f;
        #pragma unroll
        for (int q = 0; q < 8; ++q) a += s_v[tid + q * 32];
        for (int off = 16; off >= 1; off >>= 1)
            a += __shfl_down_sync(0xffffffffu, a, off);
        if (tid == 0) {
            float res = 1.f / (1.f + expf(-(a + bo[0])));
            float d = label[0] - res;
            tail[0] = d * d;
            tail[1] = res;
        }
    }
}

// ---------------- launch ------------------------------------------------------
extern "C" void kernel_launch(void* const* d_in, const int* in_sizes, int n_in,
                              void* d_out, int out_size) {
    const int*   orig   = (const int*)d_in[0];
    const int*   reply  = (const int*)d_in[1];
    const int*   lens   = (const int*)d_in[2];
    const float* label  = (const float*)d_in[3];
    const float* embed  = (const float*)d_in[4];
    const float* Wih_f  = (const float*)d_in[5];
    const float* Whh_f  = (const float*)d_in[6];
    const float* bih_f  = (const float*)d_in[7];
    const float* bhh_f  = (const float*)d_in[8];
    const float* Wih_b  = (const float*)d_in[9];
    const float* Whh_b  = (const float*)d_in[10];
    const float* bih_b  = (const float*)d_in[11];
    const float* bhh_b  = (const float*)d_in[12];
    const float* Wl     = (const float*)d_in[13];
    const float* bl     = (const float*)d_in[14];
    const float* Wo     = (const float*)d_in[15];
    const float* bo     = (const float*)d_in[16];
    float* out = (float*)d_out;

    embed_kernel<<<S, 320>>>(orig, reply, lens, embed);

    dim3 gi_grid((S + 63) / 64, G3 / 64, 2);     // 33 x 12 x 2
    gi_kernel<<<gi_grid, 256>>>(Wih_f, bih_f, Wih_b, bih_b);

    gru_kernel<<<2 * NC, GRU_T>>>(Whh_f, bhh_f, Whh_b, bhh_b);

    dim3 op_grid((S + 63) / 64, H / 64);         // 33 x 4
    outproj_kernel<<<op_grid, 256>>>(Wl, bl, out);

    scores_kernel<<<(S + 31) / 32, 256>>>(out);  // 65 blocks
    softmax_kernel<<<1, 1024>>>();
    ctxpart_kernel<<<CTXB, 256>>>(out);
    head_kernel<<<1, 256>>>(Wo, bo, label, out + S * H);
}